// round 15
// baseline (speedup 1.0000x reference)
#include <cuda_runtime.h>
#include <cuda_fp16.h>
#include <cstdint>

#define N_TOKENS 32768
#define D_MODEL  1024
#define BM 128
#define BN 128
#define BK 64
#define KITERS (D_MODEL / BK)
#define NTHREADS 256
#define A_BYTES 16384                      // 128 rows x 128B (64 fp16)
#define STAGE_BYTES A_BYTES                // A only; B comes via LDG from L2
#define SMEM_BYTES (3 * STAGE_BYTES)       // 48 KB, 2 CTAs/SM

// ---------------- device-global scratch ------------------------------------
__device__ int g_c0, g_c1m;
__device__ int g_perm[N_TOKENS];           // slot -> token
__device__ __half g_xh[(size_t)N_TOKENS * D_MODEL];          // sorted fp16 x
__device__ __half g_Wth[2][(size_t)D_MODEL * D_MODEL];       // Wt[e][n][k] fp16

// ---------------- PTX helpers ----------------------------------------------
__device__ __forceinline__ uint32_t smem_u32(const void* p) {
    uint32_t a;
    asm("{ .reg .u64 t; cvta.to.shared.u64 t, %1; cvt.u32.u64 %0, t; }"
        : "=r"(a) : "l"(p));
    return a;
}

#define CP_ASYNC16(dst, gsrc) \
    asm volatile("cp.async.cg.shared.global [%0], [%1], 16;" \
                 :: "r"(dst), "l"(gsrc) : "memory")
#define CP_COMMIT() asm volatile("cp.async.commit_group;" ::: "memory")
#define CP_WAIT(n)  asm volatile("cp.async.wait_group %0;" :: "n"(n) : "memory")

#define LDSM_X4(r0, r1, r2, r3, addr)                                          \
    asm volatile("ldmatrix.sync.aligned.m8n8.x4.shared.b16 {%0,%1,%2,%3}, [%4];" \
                 : "=r"(r0), "=r"(r1), "=r"(r2), "=r"(r3) : "r"(addr))

#define LDG32NC(r, p) \
    asm volatile("ld.global.nc.b32 %0, [%1];" : "=r"(r) : "l"(p))

#define MMA_F16(c, a, b)                                                       \
    asm volatile("mma.sync.aligned.m16n8k16.row.col.f32.f16.f16.f32 "         \
                 "{%0,%1,%2,%3}, {%4,%5,%6,%7}, {%8,%9}, {%0,%1,%2,%3};"      \
                 : "+f"((c)[0]), "+f"((c)[1]), "+f"((c)[2]), "+f"((c)[3])     \
                 : "r"((a)[0]), "r"((a)[1]), "r"((a)[2]), "r"((a)[3]),        \
                   "r"((b)[0]), "r"((b)[1]))

// B-fragment chunk load: 4 n-tiles x 2 regs, mma.m16n8k16 col-major B layout.
// bbase already encodes (n-row = bn + wn*32 + lane>>2, k-byte = 4*(lane&3)).
// nt advance = 8 rows * 2048 B; second reg = +8 k halves = +16 B.
#define LDB(bw, koff) do {                                                     \
    _Pragma("unroll")                                                          \
    for (int nt_ = 0; nt_ < 4; nt_++) {                                        \
        LDG32NC((bw)[nt_][0], bbase + (koff) + nt_ * 16384);                   \
        LDG32NC((bw)[nt_][1], bbase + (koff) + nt_ * 16384 + 16);              \
    }                                                                          \
} while (0)

// A-chunk LDSM + 16 MMAs against the given B buffer
#define CHUNK(kg, bUSE) do {                                                   \
    const uint32_t koffA = (uint32_t)(((2 * (kg) + kgaddA) ^ x7) << 4);        \
    uint32_t a_[4][4];                                                         \
    _Pragma("unroll")                                                          \
    for (int mt_ = 0; mt_ < 4; mt_++)                                          \
        LDSM_X4(a_[mt_][0], a_[mt_][1], a_[mt_][2], a_[mt_][3],                \
                St + rowAoff[mt_] + koffA);                                    \
    _Pragma("unroll")                                                          \
    for (int mt_ = 0; mt_ < 4; mt_++)                                          \
        _Pragma("unroll")                                                      \
        for (int nt_ = 0; nt_ < 4; nt_++)                                      \
            MMA_F16(acc[mt_][nt_], a_[mt_], (bUSE)[nt_]);                      \
} while (0)

// ---------------- init -------------------------------------------------------
__global__ void k_init0() { g_c0 = 0; g_c1m = 0; }

// ------- fused pre-pass: sort+convert x  AND  transpose+convert W ------------
__global__ void k_prepass(const float* __restrict__ x, const int* __restrict__ route,
                          const float* __restrict__ W1, const float* __restrict__ W2) {
    const int tid = threadIdx.x;
    if (blockIdx.x < 4096) {
        __shared__ int sslot[8];
        const int tok0 = blockIdx.x * 8;
        if (tid < 8) {
            int t = tok0 + tid;
            int slot = (route[t] == 0) ? atomicAdd(&g_c0, 1)
                                       : (N_TOKENS - 1 - atomicAdd(&g_c1m, 1));
            sslot[tid] = slot;
            g_perm[slot] = t;
        }
        __syncthreads();
        #pragma unroll
        for (int j = 0; j < 4; j++) {
            int ch   = tid + NTHREADS * j;
            int rloc = ch >> 7;
            int col8 = (ch & 127) * 8;
            const float4* src = (const float4*)(x + (size_t)(tok0 + rloc) * D_MODEL + col8);
            float4 v0 = src[0], v1 = src[1];
            union { uint4 u; __half2 h[4]; } pk;
            pk.h[0] = __float22half2_rn(make_float2(v0.x, v0.y));
            pk.h[1] = __float22half2_rn(make_float2(v0.z, v0.w));
            pk.h[2] = __float22half2_rn(make_float2(v1.x, v1.y));
            pk.h[3] = __float22half2_rn(make_float2(v1.z, v1.w));
            *(uint4*)(g_xh + (size_t)sslot[rloc] * D_MODEL + col8) = pk.u;
        }
    } else {
        __shared__ float t[32][33];
        const int idx = blockIdx.x - 4096;
        const int e   = idx >> 10;
        const int rem = idx & 1023;
        const int n0  = (rem & 31) * 32;
        const int k0  = (rem >> 5) * 32;
        const float* W = e ? W2 : W1;
        __half* Wt = g_Wth[e];
        const int tx = tid & 31, ty = tid >> 5;
        #pragma unroll
        for (int i = 0; i < 4; i++)
            t[ty + i * 8][tx] = W[(size_t)(k0 + ty + i * 8) * D_MODEL + n0 + tx];
        __syncthreads();
        #pragma unroll
        for (int i = 0; i < 4; i++)
            Wt[(size_t)(n0 + ty + i * 8) * D_MODEL + k0 + tx] = __float2half(t[tx][ty + i * 8]);
    }
}

// ---------------- fp16 mma.sync GEMM, B direct from L2 -----------------------
// A staged in smem (3 x 16KB ring, swizzled, ldmatrix). B fragments loaded
// straight from g_Wth via ld.global.nc in mma layout, ping-pong double
// buffered one k16-chunk ahead (L2 latency hidden under the previous chunk's
// MMAs). Warp grid 2m x 4n, warp tile 64 x 32.
__global__ __launch_bounds__(NTHREADS, 2)
void k_gemm(const float* __restrict__ b1, const float* __restrict__ b2,
            float* __restrict__ out)
{
    extern __shared__ __align__(128) char smem[];
    __shared__ int   srow[BM];
    __shared__ int   srt[BM];
    __shared__ float sbias[2][BN];

    const uint32_t sb  = smem_u32(smem);
    const int tid  = threadIdx.x;
    const int lane = tid & 31, wid = tid >> 5;
    const int tig  = lane & 3, gid = lane >> 2;
    const int wm   = wid >> 2, wn = wid & 3;
    const int bn   = blockIdx.x * BN, bm = blockIdx.y * BM;

    const int cnt0 = g_c0;
    if (tid < BM) {
        srow[tid] = g_perm[bm + tid];
        srt[tid]  = (bm + tid < cnt0) ? 0 : 1;
    }
    if (tid < 128) sbias[0][tid] = b1[bn + tid];
    else           sbias[1][tid - 128] = b2[bn + tid - 128];
    __syncthreads();

    const int uni   = (srt[0] == srt[BM - 1]) ? srt[0] : -1;
    const int npass = (uni >= 0) ? 1 : 2;

    // ---- A cp.async staging map: chunk ch = tid + 256*j -> row ch>>3, grp ch&7
    uint32_t dsw[4];
    uint64_t asrc[4];
    #pragma unroll
    for (int j = 0; j < 4; j++) {
        int ch = tid + NTHREADS * j;
        int r = ch >> 3, c4 = ch & 7;
        dsw[j]  = (uint32_t)((r * 8 + (c4 ^ (r & 7))) << 4);
        asrc[j] = __cvta_generic_to_global(g_xh + (size_t)(bm + r) * D_MODEL + c4 * 8);
    }

    // ---- ldmatrix per-lane addressing (A only) ----------------------------
    const int x7 = lane & 7;
    const int kgaddA = (lane >> 4) & 1;
    uint32_t rowAoff[4];
    #pragma unroll
    for (int mt = 0; mt < 4; mt++)
        rowAoff[mt] = (uint32_t)((wm * 64 + mt * 16 + ((lane >> 3) & 1) * 8 + x7) * 128);

    // ---- B LDG per-lane base (mma col-major B fragment layout) ------------
    // thread holds B rows k = 2*(lane&3)(+1) and +8, col n = lane>>2
    const uint32_t brow = (uint32_t)(bn + wn * 32 + (lane >> 2));
    const uint32_t bcol = (uint32_t)(4 * (lane & 3));     // byte offset in k

    for (int pass = 0; pass < npass; pass++) {
        const int pe = (uni >= 0) ? uni : pass;
        const uint64_t wtb = __cvta_generic_to_global(g_Wth[pe]);
        const uint64_t bbase = wtb + (uint64_t)brow * (D_MODEL * 2) + bcol;

        float acc[4][4][4];
        #pragma unroll
        for (int mt = 0; mt < 4; mt++)
            #pragma unroll
            for (int nt = 0; nt < 4; nt++)
                #pragma unroll
                for (int q = 0; q < 4; q++) acc[mt][nt][q] = 0.f;

        uint32_t bP[4][2], bQ[4][2];

        // prologue: A stages 0,1 + first B chunk
        #pragma unroll
        for (int p = 0; p < 2; p++) {
            const uint32_t so = p * STAGE_BYTES;
            const uint64_t ko = (uint64_t)p * 128;
            #pragma unroll
            for (int j = 0; j < 4; j++)
                CP_ASYNC16(sb + so + dsw[j], asrc[j] + ko);
            CP_COMMIT();
        }
        LDB(bP, 0u);

        int slot = 0, nslot = 2;
        for (int it = 0; it < KITERS; it++) {
            if (it + 1 < KITERS) { CP_WAIT(1); } else { CP_WAIT(0); }
            __syncthreads();

            if (it + 2 < KITERS) {
                const uint32_t so = (uint32_t)nslot * STAGE_BYTES;
                const uint64_t ko = (uint64_t)(it + 2) * 128;
                #pragma unroll
                for (int j = 0; j < 4; j++)
                    CP_ASYNC16(sb + so + dsw[j], asrc[j] + ko);
                CP_COMMIT();
            }

            const uint32_t St = sb + (uint32_t)slot * STAGE_BYTES;
            const uint32_t kB = (uint32_t)it * 128;     // k byte offset of BK
            // next-iter kc0 offset; wrap OOB prefetch of the very last chunk
            uint32_t kN = kB + 128;
            if (kN >= 2048) kN = 0;

            // 4 k16 chunks; B ping-pong loaded one chunk ahead
            LDB(bQ, kB + 32);  CHUNK(0, bP);
            LDB(bP, kB + 64);  CHUNK(1, bQ);
            LDB(bQ, kB + 96);  CHUNK(2, bP);
            LDB(bP, kN);       CHUNK(3, bQ);

            slot = (slot + 1) % 3;
            nslot = (nslot + 1) % 3;
        }

        // epilogue: bias + scatter to original token rows (predicated per row)
        if (pass + 1 < npass) __syncthreads();   // only needed before smem reuse
        #pragma unroll
        for (int mt = 0; mt < 4; mt++) {
            #pragma unroll
            for (int h = 0; h < 2; h++) {
                const int rr = wm * 64 + mt * 16 + gid + h * 8;
                if (uni >= 0 || srt[rr] == pe) {
                    float* op = out + (size_t)srow[rr] * D_MODEL + bn;
                    #pragma unroll
                    for (int nt = 0; nt < 4; nt++) {
                        const int c = wn * 32 + nt * 8 + 2 * tig;
                        float2 v;
                        v.x = acc[mt][nt][h * 2 + 0] + sbias[pe][c];
                        v.y = acc[mt][nt][h * 2 + 1] + sbias[pe][c + 1];
                        *(float2*)(op + c) = v;
                    }
                }
            }
        }
    }
}

// ---------------- launch -----------------------------------------------------
extern "C" void kernel_launch(void* const* d_in, const int* in_sizes, int n_in,
                              void* d_out, int out_size)
{
    const float* x     = (const float*)d_in[0];
    const float* W1    = (const float*)d_in[1];
    const float* b1    = (const float*)d_in[2];
    const float* W2    = (const float*)d_in[3];
    const float* b2    = (const float*)d_in[4];
    const int*   route = (const int*)  d_in[5];
    float*       out   = (float*)d_out;

    cudaFuncSetAttribute(k_gemm, cudaFuncAttributeMaxDynamicSharedMemorySize,
                         SMEM_BYTES);

    k_init0<<<1, 1>>>();
    k_prepass<<<6144, NTHREADS>>>(x, route, W1, W2);

    dim3 grid(D_MODEL / BN, N_TOKENS / BM);   // (8, 256)
    k_gemm<<<grid, NTHREADS, SMEM_BYTES>>>(b1, b2, out);
}

// round 16
// speedup vs baseline: 2.0214x; 2.0214x over previous
#include <cuda_runtime.h>
#include <cuda_fp16.h>
#include <cstdint>

#define N_TOKENS 32768
#define D_MODEL  1024
#define BM 128
#define BN 128
#define BK 64
#define KITERS (D_MODEL / BK)
#define NTHREADS 256
#define A_BYTES 16384                      // 128 rows x 128B (64 fp16)
#define STAGE_BYTES 32768                  // A + B
#define SMEM_BYTES (3 * STAGE_BYTES)       // 96 KB, 2 CTAs/SM

// ---------------- device-global scratch ------------------------------------
__device__ int g_c0, g_c1m;
__device__ int g_perm[N_TOKENS];           // slot -> token
__device__ __half g_xh[(size_t)N_TOKENS * D_MODEL];          // sorted fp16 x
__device__ __half g_Wth[2][(size_t)D_MODEL * D_MODEL];       // Wt[e][n][k] fp16

// ---------------- PTX helpers ----------------------------------------------
__device__ __forceinline__ uint32_t smem_u32(const void* p) {
    uint32_t a;
    asm("{ .reg .u64 t; cvta.to.shared.u64 t, %1; cvt.u32.u64 %0, t; }"
        : "=r"(a) : "l"(p));
    return a;
}

#define CP_ASYNC16(dst, gsrc) \
    asm volatile("cp.async.cg.shared.global [%0], [%1], 16;" \
                 :: "r"(dst), "l"(gsrc) : "memory")
#define CP_COMMIT() asm volatile("cp.async.commit_group;" ::: "memory")
#define CP_WAIT(n)  asm volatile("cp.async.wait_group %0;" :: "n"(n) : "memory")

#define LDSM_X4(r0, r1, r2, r3, addr)                                          \
    asm volatile("ldmatrix.sync.aligned.m8n8.x4.shared.b16 {%0,%1,%2,%3}, [%4];" \
                 : "=r"(r0), "=r"(r1), "=r"(r2), "=r"(r3) : "r"(addr))

#define MMA_F16(c, a, b)                                                       \
    asm volatile("mma.sync.aligned.m16n8k16.row.col.f32.f16.f16.f32 "         \
                 "{%0,%1,%2,%3}, {%4,%5,%6,%7}, {%8,%9}, {%0,%1,%2,%3};"      \
                 : "+f"((c)[0]), "+f"((c)[1]), "+f"((c)[2]), "+f"((c)[3])     \
                 : "r"((a)[0]), "r"((a)[1]), "r"((a)[2]), "r"((a)[3]),        \
                   "r"((b)[0]), "r"((b)[1]))

// ---------------- init -------------------------------------------------------
__global__ void k_init0() { g_c0 = 0; g_c1m = 0; }

// ------- fused pre-pass: sort+convert x  AND  transpose+convert W ------------
// Blocks 0..4095: claim slots for 8 tokens, write fp16 rows to g_xh sorted.
// Blocks 4096..6143: 32x32 transpose tile of W1/W2 -> g_Wth (fp16).
__global__ void k_prepass(const float* __restrict__ x, const int* __restrict__ route,
                          const float* __restrict__ W1, const float* __restrict__ W2) {
    const int tid = threadIdx.x;
    if (blockIdx.x < 4096) {
        __shared__ int sslot[8];
        const int tok0 = blockIdx.x * 8;
        if (tid < 8) {
            int t = tok0 + tid;
            int slot = (route[t] == 0) ? atomicAdd(&g_c0, 1)
                                       : (N_TOKENS - 1 - atomicAdd(&g_c1m, 1));
            sslot[tid] = slot;
            g_perm[slot] = t;
        }
        __syncthreads();
        #pragma unroll
        for (int j = 0; j < 4; j++) {
            int ch   = tid + NTHREADS * j;     // 0..1023 : 8 rows x 128 chunks
            int rloc = ch >> 7;
            int col8 = (ch & 127) * 8;
            const float4* src = (const float4*)(x + (size_t)(tok0 + rloc) * D_MODEL + col8);
            float4 v0 = src[0], v1 = src[1];
            union { uint4 u; __half2 h[4]; } pk;
            pk.h[0] = __float22half2_rn(make_float2(v0.x, v0.y));
            pk.h[1] = __float22half2_rn(make_float2(v0.z, v0.w));
            pk.h[2] = __float22half2_rn(make_float2(v1.x, v1.y));
            pk.h[3] = __float22half2_rn(make_float2(v1.z, v1.w));
            *(uint4*)(g_xh + (size_t)sslot[rloc] * D_MODEL + col8) = pk.u;
        }
    } else {
        __shared__ float t[32][33];
        const int idx = blockIdx.x - 4096;       // 0..2047
        const int e   = idx >> 10;               // expert
        const int rem = idx & 1023;
        const int n0  = (rem & 31) * 32;
        const int k0  = (rem >> 5) * 32;
        const float* W = e ? W2 : W1;
        __half* Wt = g_Wth[e];
        const int tx = tid & 31, ty = tid >> 5;  // (32, 8) roles
        #pragma unroll
        for (int i = 0; i < 4; i++)
            t[ty + i * 8][tx] = W[(size_t)(k0 + ty + i * 8) * D_MODEL + n0 + tx];
        __syncthreads();
        #pragma unroll
        for (int i = 0; i < 4; i++)
            Wt[(size_t)(n0 + ty + i * 8) * D_MODEL + k0 + tx] = __float2half(t[tx][ty + i * 8]);
    }
}

// ---------------- fp16 mma.sync GEMM (round-13 structure + full unroll) ------
// Stage s at s*32KB: A (128 rows x 128B = 64 fp16), B likewise.
// Row = 8 x 16B groups; logical group c4 stored at (c4 ^ (r & 7)).
// Warp grid 2m x 4n, warp tile 64 x 32. A rows SORTED (contiguous loads).
// The 16-trip mainloop is fully unrolled: ring indices, stage bases and K
// offsets constant-fold to immediates, removing the dependent integer chains
// that showed up as 8.5% alu-pipe in the round-13 profile.
__global__ __launch_bounds__(NTHREADS, 2)
void k_gemm(const float* __restrict__ b1, const float* __restrict__ b2,
            float* __restrict__ out)
{
    extern __shared__ __align__(128) char smem[];
    __shared__ int   srow[BM];
    __shared__ int   srt[BM];
    __shared__ float sbias[2][BN];

    const uint32_t sb  = smem_u32(smem);
    const int tid  = threadIdx.x;
    const int lane = tid & 31, wid = tid >> 5;
    const int tig  = lane & 3, gid = lane >> 2;
    const int wm   = wid >> 2, wn = wid & 3;
    const int bn   = blockIdx.x * BN, bm = blockIdx.y * BM;

    const int cnt0 = g_c0;
    if (tid < BM) {
        srow[tid] = g_perm[bm + tid];
        srt[tid]  = (bm + tid < cnt0) ? 0 : 1;
    }
    if (tid < 128) sbias[0][tid] = b1[bn + tid];
    else           sbias[1][tid - 128] = b2[bn + tid - 128];
    __syncthreads();

    const int uni   = (srt[0] == srt[BM - 1]) ? srt[0] : -1;
    const int npass = (uni >= 0) ? 1 : 2;

    // ---- cp.async staging maps: chunk ch = tid + 256*j -> row ch>>3, grp ch&7
    uint32_t dsw[4];
    uint64_t asrc[4];
    uint32_t bofs[4];
    #pragma unroll
    for (int j = 0; j < 4; j++) {
        int ch = tid + NTHREADS * j;
        int r = ch >> 3, c4 = ch & 7;
        dsw[j]  = (uint32_t)((r * 8 + (c4 ^ (r & 7))) << 4);
        asrc[j] = __cvta_generic_to_global(g_xh + (size_t)(bm + r) * D_MODEL + c4 * 8);
        bofs[j] = (uint32_t)(((bn + r) * D_MODEL + c4 * 8) * 2);   // byte offset
    }

    // ---- ldmatrix per-lane addressing -------------------------------------
    const int x7 = lane & 7;
    const int kgaddA = (lane >> 4) & 1;
    const int kgaddB = (lane >> 3) & 1;
    uint32_t rowAoff[4];
    #pragma unroll
    for (int mt = 0; mt < 4; mt++)
        rowAoff[mt] = (uint32_t)((wm * 64 + mt * 16 + ((lane >> 3) & 1) * 8 + x7) * 128);
    uint32_t rowBoff[2];
    #pragma unroll
    for (int np = 0; np < 2; np++)
        rowBoff[np] = (uint32_t)(A_BYTES +
                        (wn * 32 + (np * 2 + ((lane >> 4) & 1)) * 8 + x7) * 128);

    for (int pass = 0; pass < npass; pass++) {
        const int pe = (uni >= 0) ? uni : pass;
        const uint64_t wtb = __cvta_generic_to_global(g_Wth[pe]);

        float acc[4][4][4];
        #pragma unroll
        for (int mt = 0; mt < 4; mt++)
            #pragma unroll
            for (int nt = 0; nt < 4; nt++)
                #pragma unroll
                for (int q = 0; q < 4; q++) acc[mt][nt][q] = 0.f;

        // prologue: stages 0 and 1 (per-iter K advance = 64 fp16 = 128 B)
        #pragma unroll
        for (int p = 0; p < 2; p++) {
            const uint32_t so = p * STAGE_BYTES;
            const uint64_t ko = (uint64_t)p * 128;
            #pragma unroll
            for (int j = 0; j < 4; j++) {
                CP_ASYNC16(sb + so + dsw[j],           asrc[j] + ko);
                CP_ASYNC16(sb + so + A_BYTES + dsw[j], wtb + bofs[j] + ko);
            }
            CP_COMMIT();
        }

        #pragma unroll
        for (int it = 0; it < KITERS; it++) {
            const int slot  = it % 3;            // constant-folds under unroll
            const int nslot = (it + 2) % 3;
            if (it + 1 < KITERS) { CP_WAIT(1); } else { CP_WAIT(0); }
            __syncthreads();

            if (it + 2 < KITERS) {
                const uint32_t so = (uint32_t)nslot * STAGE_BYTES;
                const uint64_t ko = (uint64_t)(it + 2) * 128;
                #pragma unroll
                for (int j = 0; j < 4; j++) {
                    CP_ASYNC16(sb + so + dsw[j],           asrc[j] + ko);
                    CP_ASYNC16(sb + so + A_BYTES + dsw[j], wtb + bofs[j] + ko);
                }
                CP_COMMIT();
            }

            const uint32_t St = sb + (uint32_t)slot * STAGE_BYTES;
            #pragma unroll
            for (int kc = 0; kc < 4; kc++) {         // 4 x k16 chunks in BK=64
                const uint32_t koffA = (uint32_t)(((2 * kc + kgaddA) ^ x7) << 4);
                const uint32_t koffB = (uint32_t)(((2 * kc + kgaddB) ^ x7) << 4);
                uint32_t a[4][4], b[4][2];
                #pragma unroll
                for (int mt = 0; mt < 4; mt++)
                    LDSM_X4(a[mt][0], a[mt][1], a[mt][2], a[mt][3],
                            St + rowAoff[mt] + koffA);
                #pragma unroll
                for (int np = 0; np < 2; np++)
                    LDSM_X4(b[np * 2][0], b[np * 2][1], b[np * 2 + 1][0], b[np * 2 + 1][1],
                            St + rowBoff[np] + koffB);
                #pragma unroll
                for (int mt = 0; mt < 4; mt++)
                    #pragma unroll
                    for (int nt = 0; nt < 4; nt++)
                        MMA_F16(acc[mt][nt], a[mt], b[nt]);
            }
        }

        // epilogue: bias + scatter to original token rows (predicated per row)
        if (pass + 1 < npass) __syncthreads();   // only needed before smem reuse
        #pragma unroll
        for (int mt = 0; mt < 4; mt++) {
            #pragma unroll
            for (int h = 0; h < 2; h++) {
                const int rr = wm * 64 + mt * 16 + gid + h * 8;
                if (uni >= 0 || srt[rr] == pe) {
                    float* op = out + (size_t)srow[rr] * D_MODEL + bn;
                    #pragma unroll
                    for (int nt = 0; nt < 4; nt++) {
                        const int c = wn * 32 + nt * 8 + 2 * tig;
                        float2 v;
                        v.x = acc[mt][nt][h * 2 + 0] + sbias[pe][c];
                        v.y = acc[mt][nt][h * 2 + 1] + sbias[pe][c + 1];
                        *(float2*)(op + c) = v;
                    }
                }
            }
        }
    }
}

// ---------------- launch -----------------------------------------------------
extern "C" void kernel_launch(void* const* d_in, const int* in_sizes, int n_in,
                              void* d_out, int out_size)
{
    const float* x     = (const float*)d_in[0];
    const float* W1    = (const float*)d_in[1];
    const float* b1    = (const float*)d_in[2];
    const float* W2    = (const float*)d_in[3];
    const float* b2    = (const float*)d_in[4];
    const int*   route = (const int*)  d_in[5];
    float*       out   = (float*)d_out;

    cudaFuncSetAttribute(k_gemm, cudaFuncAttributeMaxDynamicSharedMemorySize,
                         SMEM_BYTES);

    k_init0<<<1, 1>>>();
    k_prepass<<<6144, NTHREADS>>>(x, route, W1, W2);

    dim3 grid(D_MODEL / BN, N_TOKENS / BM);   // (8, 256)
    k_gemm<<<grid, NTHREADS, SMEM_BYTES>>>(b1, b2, out);
}